// round 17
// baseline (speedup 1.0000x reference)
#include <cuda_runtime.h>
#include <cstdint>

#define N_CELLS  8388608
#define N_HALO   1048576
#define NFIELDS  12
#define BSHIFT   10
#define NBUCKETS 8192           // N_CELLS >> BSHIFT
#define HBUCKETS 4096           // buckets per half
#define CPB      1024           // cells per bucket
#define SLAB     384            // record cap per bucket (mean 183, +15 sd)
#define LOC_MASK (CPB - 1)
#define HALFBIT  0x800
#define BUF_FL   (NFIELDS * CPB)            // floats per buffer (48 KB)
#define K5_SMEM  (2 * BUF_FL * 4)           // 98304 B

__device__ int   g_cur[NBUCKETS];                      // per-bucket count
__device__ int   g_rec[NBUCKETS * SLAB];               // 12.6 MB
__device__ int   g_pos0[N_HALO];                       // slot of contrib 0 | coarse<<31
__device__ int   g_pos1[N_HALO];                       // slot of contrib 1 (valid iff coarse)
__device__ float g_cscr[(size_t)NBUCKETS * SLAB * 12]; // 151 MB

// Host-side stream/event fork-join plumbing (created once at load; host
// objects only -- no device memory).
struct HxAsync {
    cudaStream_t s2;
    cudaEvent_t  evA, ev5A;
    HxAsync() {
        cudaStreamCreateWithFlags(&s2, cudaStreamNonBlocking);
        cudaEventCreateWithFlags(&evA,  cudaEventDisableTiming);
        cudaEventCreateWithFlags(&ev5A, cudaEventDisableTiming);
    }
};
static HxAsync g_hx;

// ---------------------------------------------------------------------------
__global__ void k0_zero() { g_cur[blockIdx.x * 1024 + threadIdx.x] = 0; }

// ---------------------------------------------------------------------------
// Half-space binning: bins ONLY contributions whose cell is in half `halfId`
// (cell >> 22 == halfId -> buckets [halfId*4096, +4096)). Scans all elements.
// 32 KB static smem -> co-resides with one k5 CTA per SM.
__global__ __launch_bounds__(1024) void k_bin_half(
    const int2* __restrict__ src_idx, const float2* __restrict__ weights,
    const int halfId)
{
    __shared__ int sh_cnt[HBUCKETS];
    __shared__ int sh_base[HBUCKETS];
    const int tid   = threadIdx.x;
    const int ebase = blockIdx.x * 4096;
    const int B0    = halfId * HBUCKETS;

    for (int j = tid; j < HBUCKETS; j += 1024) sh_cnt[j] = 0;
    __syncthreads();

    int  i0[4], i1[4], l0[4], l1[4];
    bool cc[4], in0[4], in1[4];
    #pragma unroll
    for (int k = 0; k < 4; k++) {
        const int e = ebase + k * 1024 + tid;
        const int2   i = __ldcs(src_idx + e);
        const float2 w = __ldcs(weights + e);
        cc[k]  = (w.y != 0.0f);
        i0[k] = i.x;  i1[k] = i.y;
        in0[k] = ((i.x >> 22) == halfId);
        in1[k] = cc[k] && ((i.y >> 22) == halfId);
        l0[k] = in0[k] ? atomicAdd(&sh_cnt[(i.x >> BSHIFT) & (HBUCKETS-1)], 1) : 0;
        l1[k] = in1[k] ? atomicAdd(&sh_cnt[(i.y >> BSHIFT) & (HBUCKETS-1)], 1) : 0;
    }
    __syncthreads();

    for (int j = tid; j < HBUCKETS; j += 1024) {
        const int c = sh_cnt[j];
        sh_base[j] = c ? atomicAdd(&g_cur[B0 + j], c) : 0;
    }
    __syncthreads();

    #pragma unroll
    for (int k = 0; k < 4; k++) {
        const int e = ebase + k * 1024 + tid;
        if (in0[k]) {
            const int bl = (i0[k] >> BSHIFT) & (HBUCKETS-1);
            const int s0 = (B0 + bl) * SLAB + sh_base[bl] + l0[k];
            g_rec[s0] = (i0[k] & LOC_MASK) | (cc[k] ? HALFBIT : 0);
            g_pos0[e] = s0 | (cc[k] ? (int)0x80000000 : 0);
        }
        if (in1[k]) {
            const int bl = (i1[k] >> BSHIFT) & (HBUCKETS-1);
            const int s1 = (B0 + bl) * SLAB + sh_base[bl] + l1[k];
            g_rec[s1] = (i1[k] & LOC_MASK) | HALFBIT;
            g_pos1[e] = s1;
        }
    }
}

// ---------------------------------------------------------------------------
// Persistent double-buffered gather over bucket range [B0, B1): cp.async-
// stage bucket k+1's 12 field slices while serving bucket k from smem.
// Serve emits weighted 11-value records (48 B, coalesced) into g_cscr.
__global__ __launch_bounds__(256) void k5_gather(
    const float* __restrict__ fields, const int B0, const int B1)
{
    extern __shared__ float sf[];                 // 2 x BUF_FL
    const int nb = B1 - B0;
    const int c0 = B0 + (int)(((long long)blockIdx.x     * nb) / gridDim.x);
    const int c1 = B0 + (int)(((long long)(blockIdx.x+1) * nb) / gridDim.x);
    if (c0 >= c1) return;

    auto stage = [&](int buf, int b) {
        float* dst = sf + buf * BUF_FL;
        const int base = b << BSHIFT;
        for (int i = threadIdx.x; i < NFIELDS * (CPB / 4); i += 256) {
            const int f = i >> 8;                 // / (CPB/4)=256
            const int j = (i & 255) * 4;
            const float* src = fields + (size_t)f * N_CELLS + base + j;
            unsigned saddr = (unsigned)__cvta_generic_to_shared(dst + f * CPB + j);
            asm volatile("cp.async.cg.shared.global [%0], [%1], 16;\n"
                         :: "r"(saddr), "l"(src));
        }
        asm volatile("cp.async.commit_group;\n" ::: "memory");
    };

    stage(0, c0);
    for (int k = c0; k < c1; k++) {
        const int buf = (k - c0) & 1;
        if (k + 1 < c1) stage(buf ^ 1, k + 1);
        else asm volatile("cp.async.commit_group;\n" ::: "memory");
        asm volatile("cp.async.wait_group 1;\n" ::: "memory");  // buf k ready
        __syncthreads();

        const float* s = sf + buf * BUF_FL;
        const int lo = k * SLAB;
        const int n  = g_cur[k];
        for (int t = threadIdx.x; t < n; t += 256) {
            const int  rec = g_rec[lo + t];
            const int  l   = rec & LOC_MASK;
            const float w  = (rec & HALFBIT) ? 0.5f : 1.0f;

            const float u  = s[ 0*CPB + l], v  = s[ 1*CPB + l];
            const float bu = s[ 2*CPB + l], bv = s[ 3*CPB + l];
            const float h  = s[ 4*CPB + l], Hb = s[ 5*CPB + l];
            const float hh = s[ 6*CPB + l], dh = s[ 7*CPB + l];
            const float et = s[ 8*CPB + l];
            const float ku = s[ 9*CPB + l], kv = s[10*CPB + l], k3 = s[11*CPB + l];

            float4* dst = (float4*)&g_cscr[(size_t)(lo + t) * 12];
            dst[0] = make_float4(w * u,  w * v,  w * bu, w * bv);
            dst[1] = make_float4(w * h,  w * hh, w * dh, w * (h + Hb));
            dst[2] = make_float4(w * et, w * fminf(ku, k3), w * fminf(kv, k3), 0.0f);
        }
        __syncthreads();   // done reading buf before it is restaged next iter
    }
}

// ---------------------------------------------------------------------------
// Combine: per element sum its 1-2 records (fixed order r0 then r1), then
// coalesced row stores. Coarse flag lives in pos0's sign bit; pos1 is only
// read (and was written this run) when coarse. Bit-deterministic.
__global__ __launch_bounds__(256) void k6_combine(float* __restrict__ out)
{
    const int e  = blockIdx.x * 256 + threadIdx.x;
    const int p0 = g_pos0[e];
    const bool coarse = (p0 < 0);
    const int  s0 = p0 & 0x7FFFFFFF;
    const float4* r0 = (const float4*)&g_cscr[(size_t)s0 * 12];
    float4 A = __ldg(r0), B = __ldg(r0 + 1), C = __ldg(r0 + 2);
    if (coarse) {
        const int s1 = g_pos1[e];
        const float4* r1 = (const float4*)&g_cscr[(size_t)s1 * 12];
        const float4 A1 = __ldg(r1), B1 = __ldg(r1 + 1), C1 = __ldg(r1 + 2);
        A.x += A1.x; A.y += A1.y; A.z += A1.z; A.w += A1.w;
        B.x += B1.x; B.y += B1.y; B.z += B1.z; B.w += B1.w;
        C.x += C1.x; C.y += C1.y; C.z += C1.z;
    }
    out[ 0*N_HALO + e] = A.x; out[ 1*N_HALO + e] = A.y;
    out[ 2*N_HALO + e] = A.z; out[ 3*N_HALO + e] = A.w;
    out[ 4*N_HALO + e] = B.x; out[ 5*N_HALO + e] = B.y;
    out[ 6*N_HALO + e] = B.z; out[ 7*N_HALO + e] = B.w;
    out[ 8*N_HALO + e] = C.x; out[ 9*N_HALO + e] = C.y;
    out[10*N_HALO + e] = C.z;
}

extern "C" void kernel_launch(void* const* d_in, const int* in_sizes, int n_in,
                              void* d_out, int out_size)
{
    const float*  fields  = (const float*)d_in[0];
    const int2*   src_idx = (const int2*)d_in[1];
    const float2* weights = (const float2*)d_in[2];
    float*        out     = (float*)d_out;

    cudaFuncSetAttribute(k5_gather,
                         cudaFuncAttributeMaxDynamicSharedMemorySize, K5_SMEM);

    // Main stream: k0 -> binA -> binB -> k5_B ; forked stream: k5_A after binA.
    k0_zero   <<<NBUCKETS / 1024, 1024>>>();
    k_bin_half<<<256, 1024>>>(src_idx, weights, 0);
    cudaEventRecord(g_hx.evA, 0);
    cudaStreamWaitEvent(g_hx.s2, g_hx.evA, 0);
    k5_gather <<<148, 256, K5_SMEM, g_hx.s2>>>(fields, 0, HBUCKETS);
    k_bin_half<<<256, 1024>>>(src_idx, weights, 1);
    k5_gather <<<304, 256, K5_SMEM>>>(fields, HBUCKETS, NBUCKETS);
    cudaEventRecord(g_hx.ev5A, g_hx.s2);
    cudaStreamWaitEvent(0, g_hx.ev5A, 0);
    k6_combine<<<N_HALO / 256, 256>>>(out);
}